// round 4
// baseline (speedup 1.0000x reference)
#include <cuda_runtime.h>
#include <math.h>

// ---------------------------------------------------------------------------
// PowerIterationConv: sigma via Gram iteration, computed in the DFT domain.
//
//   K0: (192,192,3,3).  A(w)[o,a] = sum_s K0[o,a,s] e^{-i w.s}  (w on 17x17 grid)
//   M1(w) = A^H A.  Needed:  f0 = ||K0||_F,
//      n1 = sum_w ||M1||_F^2,  n2 = sum_w ||M1^2||_F^2,  n4 = sum_w ||M1^4||_F^2
//   With A pre-scaled by sqrt(SC2)/f0:
//      f1 = sqrt(m1/N^2)/SC2
//      f2 = sqrt(m2/N^2)/(SC2^2 f1^2)
//      ff = sqrt(m4/N^2)/(SC2^4 f1^4 f2^2)
//      sigma = f0 * f1^(1/2) * f2^(1/4) * ff^(1/8);   out = K0 / sigma
//
// Round 4: raw+swapped A planes (no dup), all-LDS.128 inner loop
// (6 LDS.128 + 32 FFMA2 per thread-kk), double-buffered smem with register
// prefetch and one barrier per k-chunk, Hermitian 6-of-9 tiles.
// ---------------------------------------------------------------------------

#define CDIM 192
#define MAT (CDIM*CDIM)          // 36864
#define NW 145                   // unique frequencies (conjugate symmetry)
#define NTOT2 289.0              // 17*17
#define SC2 48.0                 // pre-scale^2 applied to A (keeps eigs ~O(1))
#define NTILE 6                  // Hermitian: 3 diag + 3 upper tiles
#define NPART (NTILE*NW)         // 870
#define F0BLK 256

typedef unsigned long long ull;

__device__ double g_f0sq;
__device__ double g_f0part[F0BLK];
__device__ double g_part[3][NPART];
__device__ double g_inv_sigma;
__device__ float2 g_phase[NW * 9];
__device__ float2 g_bufA[NW * MAT];   // A, then G2
__device__ float2 g_bufB[NW * MAT];   // G1, then G4

__device__ __forceinline__ ull pack2(float lo, float hi) {
    ull r; asm("mov.b64 %0, {%1, %2};" : "=l"(r) : "f"(lo), "f"(hi)); return r;
}
__device__ __forceinline__ void unpack2(ull v, float& lo, float& hi) {
    asm("mov.b64 {%0, %1}, %2;" : "=f"(lo), "=f"(hi) : "l"(v));
}
__device__ __forceinline__ void ffma2(ull& d, ull a, ull b) {
    asm("fma.rn.f32x2 %0, %1, %2, %3;" : "=l"(d) : "l"(a), "l"(b), "l"(d));
}

// ---- ||K0||_F^2 partials: 256 blocks, deterministic per-block range --------
__global__ void k_f0a(const float* __restrict__ K0, int n) {
    __shared__ double sred[256];
    int per = (n + F0BLK - 1) / F0BLK;
    int base = blockIdx.x * per;
    int end = min(base + per, n);
    double s = 0.0;
    for (int i = base + threadIdx.x; i < end; i += 256) {
        float v = K0[i];
        s += (double)v * (double)v;
    }
    sred[threadIdx.x] = s;
    __syncthreads();
    for (int off = 128; off > 0; off >>= 1) {
        if (threadIdx.x < off) sred[threadIdx.x] += sred[threadIdx.x + off];
        __syncthreads();
    }
    if (threadIdx.x == 0) g_f0part[blockIdx.x] = sred[0];
}

// ---- combine f0 + build phase table (fp64 trig done once) ------------------
__global__ void k_f0b() {
    __shared__ double sred[256];
    __shared__ double s_scale;
    sred[threadIdx.x] = g_f0part[threadIdx.x];
    __syncthreads();
    for (int off = 128; off > 0; off >>= 1) {
        if (threadIdx.x < off) sred[threadIdx.x] += sred[threadIdx.x + off];
        __syncthreads();
    }
    if (threadIdx.x == 0) {
        g_f0sq = sred[0];
        s_scale = sqrt(SC2 / sred[0]);
    }
    __syncthreads();
    double sc = s_scale;
    for (int idx = threadIdx.x; idx < NW * 9; idx += 256) {
        int w = idx / 9, s = idx % 9;
        int u, v;
        if (w == 0)      { u = 0; v = 0; }
        else if (w <= 8) { u = 0; v = w; }
        else             { u = 1 + (w - 9) / 17; v = (w - 9) % 17; }
        int y = s / 3, x = s % 3;
        int m = (u * y + v * x) % 17;
        double ang = -2.0 * 3.14159265358979323846 * (double)m / 17.0;
        g_phase[idx] = make_float2((float)(cos(ang) * sc), (float)(sin(ang) * sc));
    }
}

// ---- Build A(w) = scaled DFT of K0 ----------------------------------------
__global__ void k_build(const float* __restrict__ K0) {
    int w = blockIdx.y;
    __shared__ float2 ph[9];
    if (threadIdx.x < 9) ph[threadIdx.x] = g_phase[w * 9 + threadIdx.x];
    __syncthreads();
    int idx = blockIdx.x * 256 + threadIdx.x;
    const float* kp = K0 + idx * 9;
    float re = 0.f, im = 0.f;
#pragma unroll
    for (int s = 0; s < 9; s++) {
        float k = kp[s];
        re = fmaf(k, ph[s].x, re);
        im = fmaf(k, ph[s].y, im);
    }
    g_bufA[w * MAT + idx] = make_float2(re, im);
}

// ---- Batched Hermitian gram: Y = X^H X (192x192 complex per freq) ---------
// grid (6, 145), block 256. 64x64 complex tile, 4x4 cells per thread,
// contiguous runs (rows ty*4.., cols tx*4..) -> all LDS.128.
__global__ void __launch_bounds__(256, 2) k_gram(int stage) {
    const float2* __restrict__ src = (stage == 1) ? g_bufB : g_bufA;
    float2* __restrict__ dst       = (stage == 1) ? g_bufA : g_bufB;

    int w = blockIdx.y;
    const float2* X = src + w * MAT;
    float2* Y       = dst + w * MAT;

    int t = blockIdx.x;            // (ai,bi): (0,0)(0,1)(0,2)(1,1)(1,2)(2,2)
    int ai, bi;
    if (t < 3)      { ai = 0; bi = t; }
    else if (t < 5) { ai = 1; bi = t - 2; }
    else            { ai = 2; bi = 2; }
    int a0 = ai * 64, b0 = bi * 64;

    __shared__ ull sAr[2][16][64];   // (ax,ay) raw
    __shared__ ull sAs[2][16][64];   // (ay,ax) swapped
    __shared__ ull sB [2][16][64];   // (bx,by) raw

    int tx = threadIdx.x & 15;
    int ty = (threadIdx.x >> 4) & 15;
    int lc = threadIdx.x & 63;
    int lr = threadIdx.x >> 6;       // 0..3

    ull P[16], Q[16];
#pragma unroll
    for (int c = 0; c < 16; c++) { P[c] = 0ULL; Q[c] = 0ULL; }

    float2 pa[4], pb[4];
#pragma unroll
    for (int rr = 0; rr < 4; rr++) {
        int r = lr + rr * 4;
        pa[rr] = X[r * CDIM + a0 + lc];
        pb[rr] = X[r * CDIM + b0 + lc];
    }
#pragma unroll
    for (int rr = 0; rr < 4; rr++) {
        int r = lr + rr * 4;
        sAr[0][r][lc] = pack2(pa[rr].x, pa[rr].y);
        sAs[0][r][lc] = pack2(pa[rr].y, pa[rr].x);
        sB [0][r][lc] = pack2(pb[rr].x, pb[rr].y);
    }
    __syncthreads();

    int p = 0;
    for (int it = 0; it < 12; it++) {
        if (it < 11) {
            int kc = (it + 1) * 16;
#pragma unroll
            for (int rr = 0; rr < 4; rr++) {
                int r = kc + lr + rr * 4;
                pa[rr] = X[r * CDIM + a0 + lc];
                pb[rr] = X[r * CDIM + b0 + lc];
            }
        }
#pragma unroll
        for (int kk = 0; kk < 16; kk++) {
            ulonglong2 ar0 = *(const ulonglong2*)&sAr[p][kk][ty * 4];
            ulonglong2 ar1 = *(const ulonglong2*)&sAr[p][kk][ty * 4 + 2];
            ulonglong2 as0 = *(const ulonglong2*)&sAs[p][kk][ty * 4];
            ulonglong2 as1 = *(const ulonglong2*)&sAs[p][kk][ty * 4 + 2];
            ulonglong2 bv0 = *(const ulonglong2*)&sB [p][kk][tx * 4];
            ulonglong2 bv1 = *(const ulonglong2*)&sB [p][kk][tx * 4 + 2];
            ull aR[4] = { ar0.x, ar0.y, ar1.x, ar1.y };
            ull aS[4] = { as0.x, as0.y, as1.x, as1.y };
            ull bV[4] = { bv0.x, bv0.y, bv1.x, bv1.y };
#pragma unroll
            for (int i = 0; i < 4; i++)
#pragma unroll
                for (int j = 0; j < 4; j++) {
                    ffma2(P[i * 4 + j], aR[i], bV[j]);  // (+ax*bx, +ay*by)
                    ffma2(Q[i * 4 + j], aS[i], bV[j]);  // (+ay*bx, +ax*by)
                }
        }
        if (it < 11) {
            int np = p ^ 1;
#pragma unroll
            for (int rr = 0; rr < 4; rr++) {
                int r = lr + rr * 4;
                sAr[np][r][lc] = pack2(pa[rr].x, pa[rr].y);
                sAs[np][r][lc] = pack2(pa[rr].y, pa[rr].x);
                sB [np][r][lc] = pack2(pb[rr].x, pb[rr].y);
            }
            __syncthreads();
            p = np;
        }
    }

    bool offdiag = (ai != bi);
    float ns = 0.f;
#pragma unroll
    for (int i = 0; i < 4; i++) {
        int ga = a0 + ty * 4 + i;
        float2 row[4];
#pragma unroll
        for (int j = 0; j < 4; j++) {
            float px, py, qx, qy;
            unpack2(P[i * 4 + j], px, py);
            unpack2(Q[i * 4 + j], qx, qy);
            float r  = px + py;      // ax*bx + ay*by
            float im = qy - qx;      // ax*by - ay*bx
            row[j] = make_float2(r, im);
            ns = fmaf(r, r, ns);
            ns = fmaf(im, im, ns);
        }
        int gb = b0 + tx * 4;
        *(float4*)&Y[ga * CDIM + gb]     = make_float4(row[0].x, row[0].y, row[1].x, row[1].y);
        *(float4*)&Y[ga * CDIM + gb + 2] = make_float4(row[2].x, row[2].y, row[3].x, row[3].y);
        if (offdiag) {
#pragma unroll
            for (int j = 0; j < 4; j++)
                Y[(gb + j) * CDIM + ga] = make_float2(row[j].x, -row[j].y);
        }
    }

    __shared__ double sred[256];
    sred[threadIdx.x] = (double)ns;
    __syncthreads();
    for (int off = 128; off > 0; off >>= 1) {
        if (threadIdx.x < off) sred[threadIdx.x] += sred[threadIdx.x + off];
        __syncthreads();
    }
    if (threadIdx.x == 0) {
        double wgt = ((w == 0) ? 1.0 : 2.0) * (offdiag ? 2.0 : 1.0);
        g_part[stage][w * NTILE + t] = wgt * sred[0];
    }
}

// ---- Deterministic final reduction + sigma ---------------------------------
__global__ void k_sigma() {
    __shared__ double sred[256];
    double m[3];
    for (int s = 0; s < 3; s++) {
        double acc = 0.0;
        for (int i = threadIdx.x; i < NPART; i += 256) acc += g_part[s][i];
        sred[threadIdx.x] = acc;
        __syncthreads();
        for (int off = 128; off > 0; off >>= 1) {
            if (threadIdx.x < off) sred[threadIdx.x] += sred[threadIdx.x + off];
            __syncthreads();
        }
        m[s] = sred[0];
        __syncthreads();
    }
    if (threadIdx.x == 0) {
        double f0 = sqrt(g_f0sq);
        double f1 = sqrt(m[0] / NTOT2) / SC2;
        double f2 = sqrt(m[1] / NTOT2) / (SC2 * SC2 * f1 * f1);
        double ff = sqrt(m[2] / NTOT2) /
                    (SC2 * SC2 * SC2 * SC2 * f1 * f1 * f1 * f1 * f2 * f2);
        double logs = log(f0) + 0.5 * log(f1) + 0.25 * log(f2) + 0.125 * log(ff);
        g_inv_sigma = exp(-logs);
    }
}

__global__ void k_scale(const float* __restrict__ K0, float* __restrict__ out,
                        int n) {
    float s = (float)g_inv_sigma;
    int i = blockIdx.x * 256 + threadIdx.x;
    if (i < n) out[i] = K0[i] * s;
}

extern "C" void kernel_launch(void* const* d_in, const int* in_sizes, int n_in,
                              void* d_out, int out_size) {
    const float* K0 = (const float*)d_in[0];
    float* out = (float*)d_out;
    int n = in_sizes[0];   // 331776

    k_f0a<<<F0BLK, 256>>>(K0, n);
    k_f0b<<<1, 256>>>();
    k_build<<<dim3(144, NW), 256>>>(K0);
    k_gram<<<dim3(NTILE, NW), 256>>>(0);
    k_gram<<<dim3(NTILE, NW), 256>>>(1);
    k_gram<<<dim3(NTILE, NW), 256>>>(2);
    k_sigma<<<1, 256>>>();
    k_scale<<<(n + 255) / 256, 256>>>(K0, out, n);
}

// round 6
// speedup vs baseline: 3.0459x; 3.0459x over previous
#include <cuda_runtime.h>
#include <cuda_bf16.h>
#include <math.h>
#include <stdint.h>

// ---------------------------------------------------------------------------
// PowerIterationConv: sigma via Gram iteration in the DFT domain, grams on
// tensor cores via baseline mma.sync (m16n8k16 bf16, fp32 accum) — compiles
// for plain compute_103 (no tcgen05).
//
//   A(w) = DFT of K0 at 17x17 freqs (145 unique by conjugate symmetry),
//   pre-scaled by sqrt(SC2)/f0.  Per freq: G = X^H-gram; need
//   sum_w ||G||_F^2 over 3 chained stages -> sigma (scalar algebra).
//
//   With X[a][o] planes (R, I):  Gr = R·R^T + I·I^T,  Gi = R·I^T − I·R^T.
//   G is Hermitian each stage -> 6-of-9 64x64 tiles + mirror writes.
//   bf16 2-way split (hi+lo), 3 MMAs per real product (lo·lo dropped).
// ---------------------------------------------------------------------------

#define CDIM 192
#define MAT (CDIM*CDIM)
#define NW 145
#define NTOT2 289.0
#define SC2 48.0
#define NTILE 6
#define NPART (NTILE*NW)        // 870
#define F0BLK 256

#define KCH 96                  // k-chunk (2 chunks cover K=192)
#define SROW 104                // padded bf16 row stride (208B, conflict-free)
#define PL (64*SROW)            // plane size in bf16 elems (6656)
#define SMEM_DYN (8*PL*2)       // 106496 bytes

typedef unsigned int uint32;

__device__ float g_R0[NW*MAT];
__device__ float g_I0[NW*MAT];
__device__ float g_R1[NW*MAT];
__device__ float g_I1[NW*MAT];
__device__ double g_f0sq;
__device__ double g_f0part[F0BLK];
__device__ double g_part[3][NPART];
__device__ double g_inv_sigma;
__device__ float2 g_phase[NW*9];

__device__ __forceinline__ void mma16816(float* d, const uint32* a,
                                         uint32 b0, uint32 b1) {
    asm volatile(
        "mma.sync.aligned.m16n8k16.row.col.f32.bf16.bf16.f32 "
        "{%0,%1,%2,%3}, {%4,%5,%6,%7}, {%8,%9}, {%0,%1,%2,%3};"
        : "+f"(d[0]), "+f"(d[1]), "+f"(d[2]), "+f"(d[3])
        : "r"(a[0]), "r"(a[1]), "r"(a[2]), "r"(a[3]), "r"(b0), "r"(b1));
}

__device__ __forceinline__ void split2(float a, float b, uint32& hi, uint32& lo) {
    __nv_bfloat16 ha = __float2bfloat16(a);
    __nv_bfloat16 hb = __float2bfloat16(b);
    __nv_bfloat16 la = __float2bfloat16(a - __bfloat162float(ha));
    __nv_bfloat16 lb = __float2bfloat16(b - __bfloat162float(hb));
    hi = ((uint32)__bfloat16_as_ushort(hb) << 16) | (uint32)__bfloat16_as_ushort(ha);
    lo = ((uint32)__bfloat16_as_ushort(lb) << 16) | (uint32)__bfloat16_as_ushort(la);
}

// ---- ||K0||_F^2 partials ---------------------------------------------------
__global__ void k_f0a(const float* __restrict__ K0, int n) {
    __shared__ double sred[256];
    int per = (n + F0BLK - 1) / F0BLK;
    int base = blockIdx.x * per;
    int end = min(base + per, n);
    double s = 0.0;
    for (int i = base + threadIdx.x; i < end; i += 256) {
        float v = K0[i];
        s += (double)v * (double)v;
    }
    sred[threadIdx.x] = s;
    __syncthreads();
    for (int off = 128; off > 0; off >>= 1) {
        if (threadIdx.x < off) sred[threadIdx.x] += sred[threadIdx.x + off];
        __syncthreads();
    }
    if (threadIdx.x == 0) g_f0part[blockIdx.x] = sred[0];
}

// ---- combine f0 + phase table ----------------------------------------------
__global__ void k_f0b() {
    __shared__ double sred[256];
    __shared__ double s_scale;
    sred[threadIdx.x] = g_f0part[threadIdx.x];
    __syncthreads();
    for (int off = 128; off > 0; off >>= 1) {
        if (threadIdx.x < off) sred[threadIdx.x] += sred[threadIdx.x + off];
        __syncthreads();
    }
    if (threadIdx.x == 0) {
        g_f0sq = sred[0];
        s_scale = sqrt(SC2 / sred[0]);
    }
    __syncthreads();
    double sc = s_scale;
    for (int idx = threadIdx.x; idx < NW * 9; idx += 256) {
        int w = idx / 9, s = idx % 9;
        int u, v;
        if (w == 0)      { u = 0; v = 0; }
        else if (w <= 8) { u = 0; v = w; }
        else             { u = 1 + (w - 9) / 17; v = (w - 9) % 17; }
        int y = s / 3, x = s % 3;
        int m = (u * y + v * x) % 17;
        double ang = -2.0 * 3.14159265358979323846 * (double)m / 17.0;
        g_phase[idx] = make_float2((float)(cos(ang) * sc), (float)(sin(ang) * sc));
    }
}

// ---- Build transposed DFT planes: R0[w][a][o], I0[w][a][o] -----------------
__global__ void k_build(const float* __restrict__ K0) {
    int w = blockIdx.y;
    int ot = (blockIdx.x / 12) * 16;
    int at = (blockIdx.x % 12) * 16;
    __shared__ float2 ph[9];
    __shared__ float sre[16][17], sim[16][17];
    if (threadIdx.x < 9) ph[threadIdx.x] = g_phase[w * 9 + threadIdx.x];
    __syncthreads();
    int o_l = threadIdx.x >> 4, a_l = threadIdx.x & 15;
    const float* kp = K0 + ((ot + o_l) * CDIM + at + a_l) * 9;
    float re = 0.f, im = 0.f;
#pragma unroll
    for (int s = 0; s < 9; s++) {
        float k = kp[s];
        re = fmaf(k, ph[s].x, re);
        im = fmaf(k, ph[s].y, im);
    }
    sre[o_l][a_l] = re;
    sim[o_l][a_l] = im;
    __syncthreads();
    int a2 = threadIdx.x >> 4, o2 = threadIdx.x & 15;
    int dst = w * MAT + (at + a2) * CDIM + ot + o2;
    g_R0[dst] = sre[o2][a2];
    g_I0[dst] = sim[o2][a2];
}

// ---- Tensor-core Hermitian gram --------------------------------------------
// grid (6, 145), block 256 (8 warps). Tile t -> 64x64 output tile (ai,bi).
// Warps 0-3: Gr, warps 4-7: Gi (A-side I frags negated). Each warp: 16 rows.
// smem planes (bf16, padded rows of SROW):
//   A_Rh, A_Rl, A_Ih, A_Il, B_Rh, B_Rl, B_Ih, B_Il
__global__ void __launch_bounds__(256, 2) k_gram(int stage) {
    const float* __restrict__ srcR = (stage == 1) ? g_R1 : g_R0;
    const float* __restrict__ srcI = (stage == 1) ? g_I1 : g_I0;
    float* __restrict__ dstR       = (stage == 1) ? g_R0 : g_R1;
    float* __restrict__ dstI       = (stage == 1) ? g_I0 : g_I1;

    int w = blockIdx.y;
    int t = blockIdx.x;            // (ai,bi): (0,0)(0,1)(0,2)(1,1)(1,2)(2,2)
    int ai, bi;
    if (t < 3)      { ai = 0; bi = t; }
    else if (t < 5) { ai = 1; bi = t - 2; }
    else            { ai = 2; bi = 2; }
    int a0g = ai * 64, b0g = bi * 64;

    const float* XR = srcR + w * MAT;
    const float* XI = srcI + w * MAT;

    extern __shared__ ushort sm16[];

    int tid = threadIdx.x;
    int wid = tid >> 5;
    int lane = tid & 31;
    int widx = wid & 3;
    bool isI = (wid >= 4);
    int mrow = widx * 16;
    int r  = lane >> 2;
    int cp = (lane & 3) * 2;

    float acc[8][4];
#pragma unroll
    for (int nt = 0; nt < 8; nt++)
#pragma unroll
        for (int q = 0; q < 4; q++) acc[nt][q] = 0.f;

    // plane element bases
    const int aRh = 0, aRl = PL, aIh = 2*PL, aIl = 3*PL;
    const int bxh = isI ? 6*PL : 4*PL;   // Dr: B_Rh ; Di: B_Ih
    const int bxl = isI ? 7*PL : 5*PL;
    const int byh = isI ? 4*PL : 6*PL;   // Dr: B_Ih ; Di: B_Rh
    const int byl = isI ? 5*PL : 7*PL;

    for (int c = 0; c < 2; c++) {
        int kb = c * KCH;
        // ---- load + split chunk: 64 A-rows and 64 B-rows x 96 cols ----
        for (int s = tid; s < 64 * 24; s += 256) {
            int row = s / 24, q = s % 24;
            int col = q * 4;
            float4 arv = *(const float4*)(XR + (a0g + row) * CDIM + kb + col);
            float4 aiv = *(const float4*)(XI + (a0g + row) * CDIM + kb + col);
            float4 brv = *(const float4*)(XR + (b0g + row) * CDIM + kb + col);
            float4 biv = *(const float4*)(XI + (b0g + row) * CDIM + kb + col);
            int eo = row * SROW + col;
            uint32 h0, l0, h1, l1;
            split2(arv.x, arv.y, h0, l0); split2(arv.z, arv.w, h1, l1);
            *(uint2*)&sm16[aRh + eo] = make_uint2(h0, h1);
            *(uint2*)&sm16[aRl + eo] = make_uint2(l0, l1);
            split2(aiv.x, aiv.y, h0, l0); split2(aiv.z, aiv.w, h1, l1);
            *(uint2*)&sm16[aIh + eo] = make_uint2(h0, h1);
            *(uint2*)&sm16[aIl + eo] = make_uint2(l0, l1);
            split2(brv.x, brv.y, h0, l0); split2(brv.z, brv.w, h1, l1);
            *(uint2*)&sm16[4*PL + eo] = make_uint2(h0, h1);
            *(uint2*)&sm16[5*PL + eo] = make_uint2(l0, l1);
            split2(biv.x, biv.y, h0, l0); split2(biv.z, biv.w, h1, l1);
            *(uint2*)&sm16[6*PL + eo] = make_uint2(h0, h1);
            *(uint2*)&sm16[7*PL + eo] = make_uint2(l0, l1);
        }
        __syncthreads();

        // ---- MMA over 6 k16-steps ----
#pragma unroll 1
        for (int ks = 0; ks < 6; ks++) {
            int k0 = ks * 16;
            int ab = (mrow + r) * SROW + k0 + cp;
            uint32 fRh[4], fRl[4], fIh[4], fIl[4];
            fRh[0] = *(const uint32*)&sm16[aRh + ab];
            fRh[1] = *(const uint32*)&sm16[aRh + ab + 8*SROW];
            fRh[2] = *(const uint32*)&sm16[aRh + ab + 8];
            fRh[3] = *(const uint32*)&sm16[aRh + ab + 8*SROW + 8];
            fRl[0] = *(const uint32*)&sm16[aRl + ab];
            fRl[1] = *(const uint32*)&sm16[aRl + ab + 8*SROW];
            fRl[2] = *(const uint32*)&sm16[aRl + ab + 8];
            fRl[3] = *(const uint32*)&sm16[aRl + ab + 8*SROW + 8];
            fIh[0] = *(const uint32*)&sm16[aIh + ab];
            fIh[1] = *(const uint32*)&sm16[aIh + ab + 8*SROW];
            fIh[2] = *(const uint32*)&sm16[aIh + ab + 8];
            fIh[3] = *(const uint32*)&sm16[aIh + ab + 8*SROW + 8];
            fIl[0] = *(const uint32*)&sm16[aIl + ab];
            fIl[1] = *(const uint32*)&sm16[aIl + ab + 8*SROW];
            fIl[2] = *(const uint32*)&sm16[aIl + ab + 8];
            fIl[3] = *(const uint32*)&sm16[aIl + ab + 8*SROW + 8];
            if (isI) {    // Di = R·I^T + (−I)·R^T
#pragma unroll
                for (int q = 0; q < 4; q++) {
                    fIh[q] ^= 0x80008000u;
                    fIl[q] ^= 0x80008000u;
                }
            }
#pragma unroll
            for (int nt = 0; nt < 8; nt++) {
                int bb = (nt * 8 + r) * SROW + k0 + cp;
                uint32 xh0 = *(const uint32*)&sm16[bxh + bb];
                uint32 xh1 = *(const uint32*)&sm16[bxh + bb + 8];
                uint32 xl0 = *(const uint32*)&sm16[bxl + bb];
                uint32 xl1 = *(const uint32*)&sm16[bxl + bb + 8];
                uint32 yh0 = *(const uint32*)&sm16[byh + bb];
                uint32 yh1 = *(const uint32*)&sm16[byh + bb + 8];
                uint32 yl0 = *(const uint32*)&sm16[byl + bb];
                uint32 yl1 = *(const uint32*)&sm16[byl + bb + 8];
                // Dr: R·R (hh,hl,lh) + I·I (hh,hl,lh)
                // Di: R·I (hh,hl,lh) + (−I)·R (hh,hl,lh)
                mma16816(acc[nt], fRh, xh0, xh1);
                mma16816(acc[nt], fRh, xl0, xl1);
                mma16816(acc[nt], fRl, xh0, xh1);
                mma16816(acc[nt], fIh, yh0, yh1);
                mma16816(acc[nt], fIh, yl0, yl1);
                mma16816(acc[nt], fIl, yh0, yh1);
            }
        }
        __syncthreads();
    }

    // ---- epilogue: write tile (+ conjugate mirror), Frobenius partial ----
    bool offdiag = (ai != bi);
    bool wr = (stage != 2);          // stage 2 output only feeds norms
    float sgn = isI ? -1.f : 1.f;
    float* dstM = (isI ? dstI : dstR) + w * MAT;
    float ns = 0.f;
#pragma unroll
    for (int nt = 0; nt < 8; nt++) {
        float v0 = acc[nt][0], v1 = acc[nt][1];
        float v2 = acc[nt][2], v3 = acc[nt][3];
        ns = fmaf(v0, v0, ns); ns = fmaf(v1, v1, ns);
        ns = fmaf(v2, v2, ns); ns = fmaf(v3, v3, ns);
        if (wr) {
            int gr0 = a0g + mrow + r;
            int gc0 = b0g + nt * 8 + cp;
            *(float2*)&dstM[gr0 * CDIM + gc0]       = make_float2(v0, v1);
            *(float2*)&dstM[(gr0 + 8) * CDIM + gc0] = make_float2(v2, v3);
            if (offdiag) {
                dstM[gc0 * CDIM + gr0]           = sgn * v0;
                dstM[(gc0 + 1) * CDIM + gr0]     = sgn * v1;
                dstM[gc0 * CDIM + gr0 + 8]       = sgn * v2;
                dstM[(gc0 + 1) * CDIM + gr0 + 8] = sgn * v3;
            }
        }
    }

    double* red = (double*)sm16;     // planes dead
    red[tid] = (double)ns;
    __syncthreads();
    for (int off = 128; off > 0; off >>= 1) {
        if (tid < off) red[tid] += red[tid + off];
        __syncthreads();
    }
    if (tid == 0) {
        double wgt = ((w == 0) ? 1.0 : 2.0) * (offdiag ? 2.0 : 1.0);
        g_part[stage][w * NTILE + t] = wgt * red[0];
    }
}

// ---- Deterministic final reduction + sigma ---------------------------------
__global__ void k_sigma() {
    __shared__ double sred[256];
    double m[3];
    for (int s = 0; s < 3; s++) {
        double acc = 0.0;
        for (int i = threadIdx.x; i < NPART; i += 256) acc += g_part[s][i];
        sred[threadIdx.x] = acc;
        __syncthreads();
        for (int off = 128; off > 0; off >>= 1) {
            if (threadIdx.x < off) sred[threadIdx.x] += sred[threadIdx.x + off];
            __syncthreads();
        }
        m[s] = sred[0];
        __syncthreads();
    }
    if (threadIdx.x == 0) {
        double f0 = sqrt(g_f0sq);
        double f1 = sqrt(m[0] / NTOT2) / SC2;
        double f2 = sqrt(m[1] / NTOT2) / (SC2 * SC2 * f1 * f1);
        double ff = sqrt(m[2] / NTOT2) /
                    (SC2 * SC2 * SC2 * SC2 * f1 * f1 * f1 * f1 * f2 * f2);
        double logs = log(f0) + 0.5 * log(f1) + 0.25 * log(f2) + 0.125 * log(ff);
        g_inv_sigma = exp(-logs);
    }
}

__global__ void k_scale(const float* __restrict__ K0, float* __restrict__ out,
                        int n) {
    float s = (float)g_inv_sigma;
    int i = blockIdx.x * 256 + threadIdx.x;
    if (i < n) out[i] = K0[i] * s;
}

extern "C" void kernel_launch(void* const* d_in, const int* in_sizes, int n_in,
                              void* d_out, int out_size) {
    const float* K0 = (const float*)d_in[0];
    float* out = (float*)d_out;
    int n = in_sizes[0];   // 331776

    cudaFuncSetAttribute(k_gram, cudaFuncAttributeMaxDynamicSharedMemorySize,
                         SMEM_DYN);

    k_f0a<<<F0BLK, 256>>>(K0, n);
    k_f0b<<<1, 256>>>();
    k_build<<<dim3(144, NW), 256>>>(K0);
    k_gram<<<dim3(NTILE, NW), 256, SMEM_DYN>>>(0);
    k_gram<<<dim3(NTILE, NW), 256, SMEM_DYN>>>(1);
    k_gram<<<dim3(NTILE, NW), 256, SMEM_DYN>>>(2);
    k_sigma<<<1, 256>>>();
    k_scale<<<(n + 255) / 256, 256>>>(K0, out, n);
}